// round 1
// baseline (speedup 1.0000x reference)
#include <cuda_runtime.h>
#include <cuda_bf16.h>
#include <math.h>

#define NN 100000
#define DD 64
#define NG 128

// Scratch (device globals: allocation-free rule)
__device__ __align__(16) float d_t[NN * DD];
__device__ __align__(16) float d_bufA[NN * DD];
__device__ __align__(16) float d_bufB[NN * DD];
__device__ __align__(16) float d_g[NG * DD];

__device__ __forceinline__ void red_add_v4(float* addr, float4 v) {
    asm volatile("red.global.add.v4.f32 [%0], {%1,%2,%3,%4};"
                 :: "l"(addr), "f"(v.x), "f"(v.y), "f"(v.z), "f"(v.w)
                 : "memory");
}

__global__ void zero_g_kernel() {
    int i = blockIdx.x * blockDim.x + threadIdx.x;
    if (i < NG * DD) d_g[i] = 0.0f;
}

// Fused: t = act(h) @ Wr ; out = act(h) @ Ws + br
// One warp per node row. Weights staged in smem. act = relu if relu!=0.
__global__ __launch_bounds__(256) void gemm2_kernel(
    const float* __restrict__ h, const float* __restrict__ Wr,
    const float* __restrict__ br, const float* __restrict__ Ws,
    float* __restrict__ t, float* __restrict__ out, int n, int relu)
{
    __shared__ float sWr[64 * 64];
    __shared__ float sWs[64 * 64];
    __shared__ float sbr[64];
    for (int i = threadIdx.x; i < 64 * 64; i += 256) {
        sWr[i] = Wr[i];
        sWs[i] = Ws[i];
    }
    if (threadIdx.x < 64) sbr[threadIdx.x] = br[threadIdx.x];
    __syncthreads();

    int warp = threadIdx.x >> 5;
    int lane = threadIdx.x & 31;
    int row = blockIdx.x * 8 + warp;
    if (row >= n) return;

    float h0 = h[row * 64 + lane];
    float h1 = h[row * 64 + 32 + lane];
    if (relu) { h0 = fmaxf(h0, 0.0f); h1 = fmaxf(h1, 0.0f); }

    float a0 = 0.f, a1 = 0.f, b0 = 0.f, b1 = 0.f;
#pragma unroll
    for (int k = 0; k < 32; k++) {
        float hk = __shfl_sync(0xffffffffu, h0, k);
        a0 = fmaf(hk, sWr[k * 64 + lane], a0);
        a1 = fmaf(hk, sWr[k * 64 + 32 + lane], a1);
        b0 = fmaf(hk, sWs[k * 64 + lane], b0);
        b1 = fmaf(hk, sWs[k * 64 + 32 + lane], b1);
    }
#pragma unroll
    for (int k = 0; k < 32; k++) {
        float hk = __shfl_sync(0xffffffffu, h1, k);
        a0 = fmaf(hk, sWr[(k + 32) * 64 + lane], a0);
        a1 = fmaf(hk, sWr[(k + 32) * 64 + 32 + lane], a1);
        b0 = fmaf(hk, sWs[(k + 32) * 64 + lane], b0);
        b1 = fmaf(hk, sWs[(k + 32) * 64 + 32 + lane], b1);
    }

    t[row * 64 + lane]        = a0;
    t[row * 64 + 32 + lane]   = a1;
    out[row * 64 + lane]      = b0 + sbr[lane];
    out[row * 64 + 32 + lane] = b1 + sbr[lane + 32];
}

// out[dst[e]] += t[src[e]] ; 16 threads per edge, one float4 red each.
__global__ __launch_bounds__(256) void scatter_kernel(
    const float* __restrict__ t, const int* __restrict__ src,
    const int* __restrict__ dst, float* __restrict__ out, int nE)
{
    int idx = blockIdx.x * 256 + threadIdx.x;   // nE*16 = 19.2M < 2^31
    if (idx >= nE * 16) return;
    int e = idx >> 4;
    int c = idx & 15;
    int s = __ldg(&src[e]);
    int d = __ldg(&dst[e]);
    float4 v = __ldg((const float4*)t + s * 16 + c);
    red_add_v4((float*)((float4*)out + d * 16 + c), v);
}

// g[batch[n]] += relu(h[n])
__global__ __launch_bounds__(256) void pool_kernel(
    const float* __restrict__ h, const int* __restrict__ batch, int n)
{
    int idx = blockIdx.x * 256 + threadIdx.x;
    if (idx >= n * 16) return;
    int node = idx >> 4;
    int c = idx & 15;
    int b = __ldg(&batch[node]);
    float4 v = __ldg((const float4*)h + node * 16 + c);
    v.x = fmaxf(v.x, 0.f); v.y = fmaxf(v.y, 0.f);
    v.z = fmaxf(v.z, 0.f); v.w = fmaxf(v.w, 0.f);
    red_add_v4((float*)((float4*)d_g + b * 16 + c), v);
}

// MLP head: relu(g@W1+b1) @ W2 + b2 -> log_softmax. One block, warp per graph.
__global__ __launch_bounds__(128) void head_kernel(
    const float* __restrict__ W1, const float* __restrict__ b1,
    const float* __restrict__ W2, const float* __restrict__ b2,
    float* __restrict__ out)
{
    __shared__ float sW1[64 * 64];
    __shared__ float sb1[64];
    __shared__ float sW2[64 * 3];
    __shared__ float sb2[3];
    for (int i = threadIdx.x; i < 64 * 64; i += 128) sW1[i] = W1[i];
    if (threadIdx.x < 64) sb1[threadIdx.x] = b1[threadIdx.x];
    for (int i = threadIdx.x; i < 64 * 3; i += 128) sW2[i] = W2[i];
    if (threadIdx.x < 3) sb2[threadIdx.x] = b2[threadIdx.x];
    __syncthreads();

    int warp = threadIdx.x >> 5;
    int lane = threadIdx.x & 31;

    for (int gi = warp; gi < NG; gi += 4) {
        float g0 = d_g[gi * 64 + lane];
        float g1 = d_g[gi * 64 + 32 + lane];
        float h0 = sb1[lane];
        float h1 = sb1[lane + 32];
#pragma unroll
        for (int k = 0; k < 32; k++) {
            float gk = __shfl_sync(0xffffffffu, g0, k);
            h0 = fmaf(gk, sW1[k * 64 + lane], h0);
            h1 = fmaf(gk, sW1[k * 64 + 32 + lane], h1);
        }
#pragma unroll
        for (int k = 0; k < 32; k++) {
            float gk = __shfl_sync(0xffffffffu, g1, k);
            h0 = fmaf(gk, sW1[(k + 32) * 64 + lane], h0);
            h1 = fmaf(gk, sW1[(k + 32) * 64 + 32 + lane], h1);
        }
        h0 = fmaxf(h0, 0.f);
        h1 = fmaxf(h1, 0.f);

        float l0 = h0 * sW2[lane * 3 + 0] + h1 * sW2[(lane + 32) * 3 + 0];
        float l1 = h0 * sW2[lane * 3 + 1] + h1 * sW2[(lane + 32) * 3 + 1];
        float l2 = h0 * sW2[lane * 3 + 2] + h1 * sW2[(lane + 32) * 3 + 2];
#pragma unroll
        for (int o = 16; o > 0; o >>= 1) {
            l0 += __shfl_xor_sync(0xffffffffu, l0, o);
            l1 += __shfl_xor_sync(0xffffffffu, l1, o);
            l2 += __shfl_xor_sync(0xffffffffu, l2, o);
        }
        if (lane == 0) {
            l0 += sb2[0]; l1 += sb2[1]; l2 += sb2[2];
            float m = fmaxf(l0, fmaxf(l1, l2));
            float lse = m + logf(expf(l0 - m) + expf(l1 - m) + expf(l2 - m));
            out[gi * 3 + 0] = l0 - lse;
            out[gi * 3 + 1] = l1 - lse;
            out[gi * 3 + 2] = l2 - lse;
        }
    }
}

extern "C" void kernel_launch(void* const* d_in, const int* in_sizes, int n_in,
                              void* d_out, int out_size)
{
    const float* x     = (const float*)d_in[0];
    const int*   ei    = (const int*)  d_in[1];
    const int*   batch = (const int*)  d_in[2];
    const float* Wr1 = (const float*)d_in[3];
    const float* br1 = (const float*)d_in[4];
    const float* Ws1 = (const float*)d_in[5];
    const float* Wr2 = (const float*)d_in[6];
    const float* br2 = (const float*)d_in[7];
    const float* Ws2 = (const float*)d_in[8];
    const float* Wr3 = (const float*)d_in[9];
    const float* br3 = (const float*)d_in[10];
    const float* Ws3 = (const float*)d_in[11];
    const float* Wf1 = (const float*)d_in[12];
    const float* bf1 = (const float*)d_in[13];
    const float* Wf2 = (const float*)d_in[14];
    const float* bf2 = (const float*)d_in[15];

    int n = in_sizes[0] / DD;     // 100000
    int E = in_sizes[1] / 2;      // 1200000
    const int* src = ei;
    const int* dst = ei + E;

    float *t, *bufA, *bufB;
    cudaGetSymbolAddress((void**)&t,    d_t);
    cudaGetSymbolAddress((void**)&bufA, d_bufA);
    cudaGetSymbolAddress((void**)&bufB, d_bufB);

    int gemm_grid    = (n + 7) / 8;
    int scatter_grid = (E * 16 + 255) / 256;
    int pool_grid    = (n * 16 + 255) / 256;

    // Layer 1: input x, no relu on load
    gemm2_kernel<<<gemm_grid, 256>>>(x, Wr1, br1, Ws1, t, bufA, n, 0);
    scatter_kernel<<<scatter_grid, 256>>>(t, src, dst, bufA, E);
    // Layer 2 (relu of layer-1 output folded into load)
    gemm2_kernel<<<gemm_grid, 256>>>(bufA, Wr2, br2, Ws2, t, bufB, n, 1);
    scatter_kernel<<<scatter_grid, 256>>>(t, src, dst, bufB, E);
    // Layer 3
    gemm2_kernel<<<gemm_grid, 256>>>(bufB, Wr3, br3, Ws3, t, bufA, n, 1);
    scatter_kernel<<<scatter_grid, 256>>>(t, src, dst, bufA, E);

    // Global add pool (relu folded into load), then head
    zero_g_kernel<<<32, 256>>>();
    pool_kernel<<<pool_grid, 256>>>(bufA, batch, n);
    head_kernel<<<1, 128>>>(Wf1, bf1, Wf2, bf2, (float*)d_out);
}

// round 2
// speedup vs baseline: 2.0303x; 2.0303x over previous
#include <cuda_runtime.h>
#include <cuda_bf16.h>
#include <math.h>

#define NN 100000
#define DD 64
#define NG 128
#define BM 128
#define KC 32

// Scratch (device globals: allocation-free rule)
__device__ __align__(16) float d_t[NN * DD];
__device__ __align__(16) float d_bufA[NN * DD];
__device__ __align__(16) float d_bufB[NN * DD];
__device__ __align__(16) float d_g[NG * DD];

__device__ __forceinline__ void red_add_v4(float* addr, float4 v) {
    asm volatile("red.global.add.v4.f32 [%0], {%1,%2,%3,%4};"
                 :: "l"(addr), "f"(v.x), "f"(v.y), "f"(v.z), "f"(v.w)
                 : "memory");
}

// packed fp32x2 helpers (Blackwell f32x2 pipe; ptxas never auto-fuses these)
__device__ __forceinline__ unsigned long long pack2(float lo, float hi) {
    unsigned long long r;
    asm("mov.b64 %0, {%1,%2};" : "=l"(r) : "f"(lo), "f"(hi));
    return r;
}
__device__ __forceinline__ void ffma2(unsigned long long& d,
                                      unsigned long long a,
                                      unsigned long long b) {
    asm("fma.rn.f32x2 %0, %1, %2, %0;" : "+l"(d) : "l"(a), "l"(b));
}
__device__ __forceinline__ float2 unpack2(unsigned long long v) {
    float2 r;
    asm("mov.b64 {%0,%1}, %2;" : "=f"(r.x), "=f"(r.y) : "l"(v));
    return r;
}

__global__ void zero_g_kernel() {
    int i = blockIdx.x * blockDim.x + threadIdx.x;
    if (i < NG * DD) d_g[i] = 0.0f;
}

// Fused dual-GEMM: t = act(h)@Wr ; out = act(h)@Ws + br
// Tile: BM=128 rows x 128 cols (Wr cols 0-63 | Ws cols 64-127), K chunks of 32.
// 256 threads, 8x8 micro-tile per thread, f32x2 packed FMA on column pairs.
__global__ __launch_bounds__(256, 2) void gemm2_kernel(
    const float* __restrict__ h, const float* __restrict__ Wr,
    const float* __restrict__ br, const float* __restrict__ Ws,
    float* __restrict__ t, float* __restrict__ out, int n, int relu)
{
    __shared__ float sA[KC][BM + 4];   // transposed A chunk: sA[k][m]
    __shared__ float sW[KC][128];      // weight chunk: sW[k][c] (c<64: Wr, else Ws)

    const int tid = threadIdx.x;
    const int tx = tid & 15;    // col group: cols tx*8 .. +7
    const int ty = tid >> 4;    // row group: rows ty*8 .. +7
    const int row0 = blockIdx.x * BM;

    unsigned long long acc[8][4];
#pragma unroll
    for (int i = 0; i < 8; i++)
#pragma unroll
        for (int j = 0; j < 4; j++) acc[i][j] = 0ULL;

#pragma unroll
    for (int kc = 0; kc < 64; kc += KC) {
        // Stage A chunk transposed: 128 rows x 32 k = 1024 float4 loads / 256 thr
#pragma unroll
        for (int it = 0; it < 4; it++) {
            int lin = tid + it * 256;       // 0..1023
            int m  = lin >> 3;              // 0..127
            int k4 = (lin & 7) << 2;        // 0,4,..,28
            float4 v = make_float4(0.f, 0.f, 0.f, 0.f);
            int gr = row0 + m;
            if (gr < n) v = *(const float4*)(h + gr * 64 + kc + k4);
            if (relu) {
                v.x = fmaxf(v.x, 0.f); v.y = fmaxf(v.y, 0.f);
                v.z = fmaxf(v.z, 0.f); v.w = fmaxf(v.w, 0.f);
            }
            sA[k4 + 0][m] = v.x; sA[k4 + 1][m] = v.y;
            sA[k4 + 2][m] = v.z; sA[k4 + 3][m] = v.w;
        }
        // Stage W chunk: 32 k x 128 cols = 1024 float4 / 256 thr
#pragma unroll
        for (int it = 0; it < 4; it++) {
            int lin = tid + it * 256;
            int k  = lin >> 5;              // 0..31
            int c4 = (lin & 31) << 2;       // 0..124
            const float* Wp = (c4 < 64) ? (Wr + (kc + k) * 64 + c4)
                                        : (Ws + (kc + k) * 64 + (c4 - 64));
            *(float4*)&sW[k][c4] = *(const float4*)Wp;
        }
        __syncthreads();

#pragma unroll
        for (int k = 0; k < KC; k++) {
            float4 a0 = *(float4*)&sA[k][ty * 8];
            float4 a1 = *(float4*)&sA[k][ty * 8 + 4];
            float4 b0 = *(float4*)&sW[k][tx * 8];
            float4 b1 = *(float4*)&sW[k][tx * 8 + 4];
            unsigned long long bp0 = pack2(b0.x, b0.y);
            unsigned long long bp1 = pack2(b0.z, b0.w);
            unsigned long long bp2 = pack2(b1.x, b1.y);
            unsigned long long bp3 = pack2(b1.z, b1.w);
            float ar[8] = {a0.x, a0.y, a0.z, a0.w, a1.x, a1.y, a1.z, a1.w};
#pragma unroll
            for (int i = 0; i < 8; i++) {
                unsigned long long ap = pack2(ar[i], ar[i]);
                ffma2(acc[i][0], ap, bp0);
                ffma2(acc[i][1], ap, bp1);
                ffma2(acc[i][2], ap, bp2);
                ffma2(acc[i][3], ap, bp3);
            }
        }
        __syncthreads();
    }

    // Epilogue: tx<8 -> t cols tx*8..; tx>=8 -> out cols (tx*8-64).. + br
    const int c0 = tx * 8;
    float bias[8];
    if (c0 >= 64) {
#pragma unroll
        for (int j = 0; j < 8; j++) bias[j] = __ldg(&br[c0 - 64 + j]);
    }
#pragma unroll
    for (int i = 0; i < 8; i++) {
        int gr = row0 + ty * 8 + i;
        if (gr >= n) break;
        float2 v0 = unpack2(acc[i][0]);
        float2 v1 = unpack2(acc[i][1]);
        float2 v2 = unpack2(acc[i][2]);
        float2 v3 = unpack2(acc[i][3]);
        if (c0 < 64) {
            *(float4*)(t + gr * 64 + c0)     = make_float4(v0.x, v0.y, v1.x, v1.y);
            *(float4*)(t + gr * 64 + c0 + 4) = make_float4(v2.x, v2.y, v3.x, v3.y);
        } else {
            int cc = c0 - 64;
            *(float4*)(out + gr * 64 + cc)     = make_float4(v0.x + bias[0], v0.y + bias[1],
                                                             v1.x + bias[2], v1.y + bias[3]);
            *(float4*)(out + gr * 64 + cc + 4) = make_float4(v2.x + bias[4], v2.y + bias[5],
                                                             v3.x + bias[6], v3.y + bias[7]);
        }
    }
}

// out[dst[e]] += t[src[e]] ; 16 threads per edge, one float4 red each.
__global__ __launch_bounds__(256) void scatter_kernel(
    const float* __restrict__ t, const int* __restrict__ src,
    const int* __restrict__ dst, float* __restrict__ out, int nE)
{
    int idx = blockIdx.x * 256 + threadIdx.x;
    if (idx >= nE * 16) return;
    int e = idx >> 4;
    int c = idx & 15;
    int s = __ldg(&src[e]);
    int d = __ldg(&dst[e]);
    float4 v = __ldg((const float4*)t + s * 16 + c);
    red_add_v4((float*)((float4*)out + d * 16 + c), v);
}

// g[batch[n]] += relu(h[n])
__global__ __launch_bounds__(256) void pool_kernel(
    const float* __restrict__ h, const int* __restrict__ batch, int n)
{
    int idx = blockIdx.x * 256 + threadIdx.x;
    if (idx >= n * 16) return;
    int node = idx >> 4;
    int c = idx & 15;
    int b = __ldg(&batch[node]);
    float4 v = __ldg((const float4*)h + node * 16 + c);
    v.x = fmaxf(v.x, 0.f); v.y = fmaxf(v.y, 0.f);
    v.z = fmaxf(v.z, 0.f); v.w = fmaxf(v.w, 0.f);
    red_add_v4((float*)((float4*)d_g + b * 16 + c), v);
}

// MLP head: relu(g@W1+b1) @ W2 + b2 -> log_softmax. 32 blocks, warp per graph.
__global__ __launch_bounds__(128) void head_kernel(
    const float* __restrict__ W1, const float* __restrict__ b1,
    const float* __restrict__ W2, const float* __restrict__ b2,
    float* __restrict__ out)
{
    __shared__ float sW1[64 * 64];
    __shared__ float sb1[64];
    __shared__ float sW2[64 * 3];
    __shared__ float sb2[3];
    for (int i = threadIdx.x; i < 64 * 64; i += 128) sW1[i] = W1[i];
    if (threadIdx.x < 64) sb1[threadIdx.x] = b1[threadIdx.x];
    for (int i = threadIdx.x; i < 64 * 3; i += 128) sW2[i] = W2[i];
    if (threadIdx.x < 3) sb2[threadIdx.x] = b2[threadIdx.x];
    __syncthreads();

    int warp = threadIdx.x >> 5;
    int lane = threadIdx.x & 31;
    int gi = blockIdx.x * 4 + warp;
    if (gi >= NG) return;

    float g0 = d_g[gi * 64 + lane];
    float g1 = d_g[gi * 64 + 32 + lane];
    float h0 = sb1[lane];
    float h1 = sb1[lane + 32];
#pragma unroll
    for (int k = 0; k < 32; k++) {
        float gk = __shfl_sync(0xffffffffu, g0, k);
        h0 = fmaf(gk, sW1[k * 64 + lane], h0);
        h1 = fmaf(gk, sW1[k * 64 + 32 + lane], h1);
    }
#pragma unroll
    for (int k = 0; k < 32; k++) {
        float gk = __shfl_sync(0xffffffffu, g1, k);
        h0 = fmaf(gk, sW1[(k + 32) * 64 + lane], h0);
        h1 = fmaf(gk, sW1[(k + 32) * 64 + 32 + lane], h1);
    }
    h0 = fmaxf(h0, 0.f);
    h1 = fmaxf(h1, 0.f);

    float l0 = h0 * sW2[lane * 3 + 0] + h1 * sW2[(lane + 32) * 3 + 0];
    float l1 = h0 * sW2[lane * 3 + 1] + h1 * sW2[(lane + 32) * 3 + 1];
    float l2 = h0 * sW2[lane * 3 + 2] + h1 * sW2[(lane + 32) * 3 + 2];
#pragma unroll
    for (int o = 16; o > 0; o >>= 1) {
        l0 += __shfl_xor_sync(0xffffffffu, l0, o);
        l1 += __shfl_xor_sync(0xffffffffu, l1, o);
        l2 += __shfl_xor_sync(0xffffffffu, l2, o);
    }
    if (lane == 0) {
        l0 += sb2[0]; l1 += sb2[1]; l2 += sb2[2];
        float m = fmaxf(l0, fmaxf(l1, l2));
        float lse = m + logf(expf(l0 - m) + expf(l1 - m) + expf(l2 - m));
        out[gi * 3 + 0] = l0 - lse;
        out[gi * 3 + 1] = l1 - lse;
        out[gi * 3 + 2] = l2 - lse;
    }
}

extern "C" void kernel_launch(void* const* d_in, const int* in_sizes, int n_in,
                              void* d_out, int out_size)
{
    const float* x     = (const float*)d_in[0];
    const int*   ei    = (const int*)  d_in[1];
    const int*   batch = (const int*)  d_in[2];
    const float* Wr1 = (const float*)d_in[3];
    const float* br1 = (const float*)d_in[4];
    const float* Ws1 = (const float*)d_in[5];
    const float* Wr2 = (const float*)d_in[6];
    const float* br2 = (const float*)d_in[7];
    const float* Ws2 = (const float*)d_in[8];
    const float* Wr3 = (const float*)d_in[9];
    const float* br3 = (const float*)d_in[10];
    const float* Ws3 = (const float*)d_in[11];
    const float* Wf1 = (const float*)d_in[12];
    const float* bf1 = (const float*)d_in[13];
    const float* Wf2 = (const float*)d_in[14];
    const float* bf2 = (const float*)d_in[15];

    int n = in_sizes[0] / DD;     // 100000
    int E = in_sizes[1] / 2;      // 1200000
    const int* src = ei;
    const int* dst = ei + E;

    float *t, *bufA, *bufB;
    cudaGetSymbolAddress((void**)&t,    d_t);
    cudaGetSymbolAddress((void**)&bufA, d_bufA);
    cudaGetSymbolAddress((void**)&bufB, d_bufB);

    int gemm_grid    = (n + BM - 1) / BM;
    int scatter_grid = (E * 16 + 255) / 256;
    int pool_grid    = (n * 16 + 255) / 256;

    // Layer 1: input x, no relu on load
    gemm2_kernel<<<gemm_grid, 256>>>(x, Wr1, br1, Ws1, t, bufA, n, 0);
    scatter_kernel<<<scatter_grid, 256>>>(t, src, dst, bufA, E);
    // Layer 2 (relu of layer-1 output folded into load)
    gemm2_kernel<<<gemm_grid, 256>>>(bufA, Wr2, br2, Ws2, t, bufB, n, 1);
    scatter_kernel<<<scatter_grid, 256>>>(t, src, dst, bufB, E);
    // Layer 3
    gemm2_kernel<<<gemm_grid, 256>>>(bufB, Wr3, br3, Ws3, t, bufA, n, 1);
    scatter_kernel<<<scatter_grid, 256>>>(t, src, dst, bufA, E);

    // Global add pool (relu folded into load), then head
    zero_g_kernel<<<32, 256>>>();
    pool_kernel<<<pool_grid, 256>>>(bufA, batch, n);
    head_kernel<<<32, 128>>>(Wf1, bf1, Wf2, bf2, (float*)d_out);
}

// round 3
// speedup vs baseline: 2.4411x; 1.2023x over previous
#include <cuda_runtime.h>
#include <cuda_bf16.h>
#include <math.h>

#define NN 100000
#define NE 1200000
#define DD 64
#define NG 128
#define BM 128
#define KC 32

// Scratch (device globals: allocation-free rule)
__device__ __align__(16) float d_t[NN * DD];
__device__ __align__(16) float d_bufA[NN * DD];
__device__ __align__(16) float d_bufB[NN * DD];
__device__ __align__(16) float d_g[NG * DD];

// CSR scratch
__device__ int d_cnt[NN];
__device__ int d_rowptr[NN + 1];
__device__ int d_cursor[NN];
__device__ int d_col[NE];
__device__ int d_bsum[128];
__device__ int d_boff[128];

typedef unsigned long long ull;

__device__ __forceinline__ void red_add_v2(float* addr, float a, float b) {
    asm volatile("red.global.add.v2.f32 [%0], {%1,%2};"
                 :: "l"(addr), "f"(a), "f"(b) : "memory");
}

// packed fp32x2 helpers
__device__ __forceinline__ ull pack2(float lo, float hi) {
    ull r; asm("mov.b64 %0, {%1,%2};" : "=l"(r) : "f"(lo), "f"(hi)); return r;
}
__device__ __forceinline__ void ffma2(ull& d, ull a, ull b) {
    asm("fma.rn.f32x2 %0, %1, %2, %0;" : "+l"(d) : "l"(a), "l"(b));
}
__device__ __forceinline__ void fadd2(ull& d, ull v) {
    asm("add.rn.f32x2 %0, %0, %1;" : "+l"(d) : "l"(v));
}
__device__ __forceinline__ float2 unpack2(ull v) {
    float2 r; asm("mov.b64 {%0,%1}, %2;" : "=f"(r.x), "=f"(r.y) : "l"(v)); return r;
}

// ---------------- CSR build ----------------

__global__ void zero_kernel() {
    int i = blockIdx.x * blockDim.x + threadIdx.x;
    if (i < NN) d_cnt[i] = 0;
    if (i < NG * DD) d_g[i] = 0.0f;
}

__global__ void hist_kernel(const int* __restrict__ dst, int E) {
    int e = blockIdx.x * 256 + threadIdx.x;
    if (e < E) atomicAdd(&d_cnt[dst[e]], 1);
}

// Block-level exclusive scan (1024 threads/block). Writes per-block exclusive
// prefix into d_rowptr, block totals into d_bsum.
__global__ __launch_bounds__(1024) void scan1_kernel(int n) {
    __shared__ int ws[32];
    int i = blockIdx.x * 1024 + threadIdx.x;
    int lane = threadIdx.x & 31, wid = threadIdx.x >> 5;
    int c = (i < n) ? d_cnt[i] : 0;
    int v = c;
#pragma unroll
    for (int o = 1; o < 32; o <<= 1) {
        int t = __shfl_up_sync(0xffffffffu, v, o);
        if (lane >= o) v += t;
    }
    if (lane == 31) ws[wid] = v;
    __syncthreads();
    if (wid == 0) {
        int w = ws[lane];
#pragma unroll
        for (int o = 1; o < 32; o <<= 1) {
            int t = __shfl_up_sync(0xffffffffu, w, o);
            if (lane >= o) w += t;
        }
        ws[lane] = w;
    }
    __syncthreads();
    int excl = v - c + (wid > 0 ? ws[wid - 1] : 0);
    if (i < n) d_rowptr[i] = excl;
    if (threadIdx.x == 0) d_bsum[blockIdx.x] = ws[31];
}

// Scan the (<=128) block sums. One block of 128 threads.
__global__ __launch_bounds__(128) void scan2_kernel(int nb) {
    __shared__ int ws[4];
    int i = threadIdx.x;
    int lane = i & 31, wid = i >> 5;
    int c = (i < nb) ? d_bsum[i] : 0;
    int v = c;
#pragma unroll
    for (int o = 1; o < 32; o <<= 1) {
        int t = __shfl_up_sync(0xffffffffu, v, o);
        if (lane >= o) v += t;
    }
    if (lane == 31) ws[wid] = v;
    __syncthreads();
    if (wid == 0 && lane < 4) {
        int w = ws[lane];
#pragma unroll
        for (int o = 1; o < 4; o <<= 1) {
            int t = __shfl_up_sync(0x0000000fu, w, o);
            if (lane >= o) w += t;
        }
        ws[lane] = w;
    }
    __syncthreads();
    int excl = v - c + (wid > 0 ? ws[wid - 1] : 0);
    if (i < nb) d_boff[i] = excl;
}

__global__ __launch_bounds__(1024) void scan3_kernel(int n, int E) {
    int i = blockIdx.x * 1024 + threadIdx.x;
    if (i < n) {
        int r = d_rowptr[i] + d_boff[blockIdx.x];
        d_rowptr[i] = r;
        d_cursor[i] = r;
    }
    if (i == n) d_rowptr[n] = E;
}

__global__ void fill_kernel(const int* __restrict__ src,
                            const int* __restrict__ dst, int E) {
    int e = blockIdx.x * 256 + threadIdx.x;
    if (e < E) {
        int d = dst[e];
        int slot = atomicAdd(&d_cursor[d], 1);
        d_col[slot] = src[e];
    }
}

// ---------------- compute kernels ----------------

// Fused dual-GEMM: t = h@Wr ; out = h@Ws + br
__global__ __launch_bounds__(256, 2) void gemm2_kernel(
    const float* __restrict__ h, const float* __restrict__ Wr,
    const float* __restrict__ br, const float* __restrict__ Ws,
    float* __restrict__ t, float* __restrict__ out, int n)
{
    __shared__ float sA[KC][BM + 4];
    __shared__ float sW[KC][128];

    const int tid = threadIdx.x;
    const int tx = tid & 15;
    const int ty = tid >> 4;
    const int row0 = blockIdx.x * BM;

    ull acc[8][4];
#pragma unroll
    for (int i = 0; i < 8; i++)
#pragma unroll
        for (int j = 0; j < 4; j++) acc[i][j] = 0ULL;

#pragma unroll
    for (int kc = 0; kc < 64; kc += KC) {
#pragma unroll
        for (int it = 0; it < 4; it++) {
            int lin = tid + it * 256;
            int m  = lin >> 3;
            int k4 = (lin & 7) << 2;
            float4 v = make_float4(0.f, 0.f, 0.f, 0.f);
            int gr = row0 + m;
            if (gr < n) v = *(const float4*)(h + gr * 64 + kc + k4);
            sA[k4 + 0][m] = v.x; sA[k4 + 1][m] = v.y;
            sA[k4 + 2][m] = v.z; sA[k4 + 3][m] = v.w;
        }
#pragma unroll
        for (int it = 0; it < 4; it++) {
            int lin = tid + it * 256;
            int k  = lin >> 5;
            int c4 = (lin & 31) << 2;
            const float* Wp = (c4 < 64) ? (Wr + (kc + k) * 64 + c4)
                                        : (Ws + (kc + k) * 64 + (c4 - 64));
            *(float4*)&sW[k][c4] = *(const float4*)Wp;
        }
        __syncthreads();

#pragma unroll
        for (int k = 0; k < KC; k++) {
            float4 a0 = *(float4*)&sA[k][ty * 8];
            float4 a1 = *(float4*)&sA[k][ty * 8 + 4];
            float4 b0 = *(float4*)&sW[k][tx * 8];
            float4 b1 = *(float4*)&sW[k][tx * 8 + 4];
            ull bp0 = pack2(b0.x, b0.y);
            ull bp1 = pack2(b0.z, b0.w);
            ull bp2 = pack2(b1.x, b1.y);
            ull bp3 = pack2(b1.z, b1.w);
            float ar[8] = {a0.x, a0.y, a0.z, a0.w, a1.x, a1.y, a1.z, a1.w};
#pragma unroll
            for (int i = 0; i < 8; i++) {
                ull ap = pack2(ar[i], ar[i]);
                ffma2(acc[i][0], ap, bp0);
                ffma2(acc[i][1], ap, bp1);
                ffma2(acc[i][2], ap, bp2);
                ffma2(acc[i][3], ap, bp3);
            }
        }
        __syncthreads();
    }

    const int c0 = tx * 8;
    float bias[8];
    if (c0 >= 64) {
#pragma unroll
        for (int j = 0; j < 8; j++) bias[j] = __ldg(&br[c0 - 64 + j]);
    }
#pragma unroll
    for (int i = 0; i < 8; i++) {
        int gr = row0 + ty * 8 + i;
        if (gr >= n) break;
        float2 v0 = unpack2(acc[i][0]);
        float2 v1 = unpack2(acc[i][1]);
        float2 v2 = unpack2(acc[i][2]);
        float2 v3 = unpack2(acc[i][3]);
        if (c0 < 64) {
            *(float4*)(t + gr * 64 + c0)     = make_float4(v0.x, v0.y, v1.x, v1.y);
            *(float4*)(t + gr * 64 + c0 + 4) = make_float4(v2.x, v2.y, v3.x, v3.y);
        } else {
            int cc = c0 - 64;
            *(float4*)(out + gr * 64 + cc)     = make_float4(v0.x + bias[0], v0.y + bias[1],
                                                             v1.x + bias[2], v1.y + bias[3]);
            *(float4*)(out + gr * 64 + cc + 4) = make_float4(v2.x + bias[4], v2.y + bias[5],
                                                             v3.x + bias[6], v3.y + bias[7]);
        }
    }
}

// Atomic-free gather: warp per node. acc = base[node] + sum_{e in CSR[node]} t[col[e]]
// mode 0: out[node] = relu(acc).  mode 1: d_g[batch[node]] += relu(acc) (no out write).
__global__ __launch_bounds__(256) void gather_kernel(
    const float* __restrict__ t, const float* __restrict__ base,
    float* __restrict__ out, const int* __restrict__ batch, int n, int mode)
{
    int warp = threadIdx.x >> 5;
    int lane = threadIdx.x & 31;
    int node = blockIdx.x * 8 + warp;
    if (node >= n) return;

    int s0 = d_rowptr[node];
    int s1 = d_rowptr[node + 1];

    const ull* t2 = (const ull*)t;
    ull acc = ((const ull*)base)[node * 32 + lane];

    for (int j = s0; j < s1; j += 32) {
        int rem = s1 - j;
        int id = 0;
        if (lane < rem) id = d_col[j + lane];
        int cnt = rem < 32 ? rem : 32;
        for (int i = 0; i < cnt; i++) {
            int s = __shfl_sync(0xffffffffu, id, i);
            fadd2(acc, t2[s * 32 + lane]);
        }
    }

    float2 v = unpack2(acc);
    v.x = fmaxf(v.x, 0.0f);
    v.y = fmaxf(v.y, 0.0f);
    if (mode == 0) {
        ((float2*)out)[node * 32 + lane] = v;
    } else {
        int b = __ldg(&batch[node]);
        red_add_v2(&d_g[b * 64 + lane * 2], v.x, v.y);
    }
}

// MLP head: relu(g@W1+b1) @ W2 + b2 -> log_softmax. 32 blocks, warp per graph.
__global__ __launch_bounds__(128) void head_kernel(
    const float* __restrict__ W1, const float* __restrict__ b1,
    const float* __restrict__ W2, const float* __restrict__ b2,
    float* __restrict__ out)
{
    __shared__ float sW1[64 * 64];
    __shared__ float sb1[64];
    __shared__ float sW2[64 * 3];
    __shared__ float sb2[3];
    for (int i = threadIdx.x; i < 64 * 64; i += 128) sW1[i] = W1[i];
    if (threadIdx.x < 64) sb1[threadIdx.x] = b1[threadIdx.x];
    for (int i = threadIdx.x; i < 64 * 3; i += 128) sW2[i] = W2[i];
    if (threadIdx.x < 3) sb2[threadIdx.x] = b2[threadIdx.x];
    __syncthreads();

    int warp = threadIdx.x >> 5;
    int lane = threadIdx.x & 31;
    int gi = blockIdx.x * 4 + warp;
    if (gi >= NG) return;

    float g0 = d_g[gi * 64 + lane];
    float g1 = d_g[gi * 64 + 32 + lane];
    float h0 = sb1[lane];
    float h1 = sb1[lane + 32];
#pragma unroll
    for (int k = 0; k < 32; k++) {
        float gk = __shfl_sync(0xffffffffu, g0, k);
        h0 = fmaf(gk, sW1[k * 64 + lane], h0);
        h1 = fmaf(gk, sW1[k * 64 + 32 + lane], h1);
    }
#pragma unroll
    for (int k = 0; k < 32; k++) {
        float gk = __shfl_sync(0xffffffffu, g1, k);
        h0 = fmaf(gk, sW1[(k + 32) * 64 + lane], h0);
        h1 = fmaf(gk, sW1[(k + 32) * 64 + 32 + lane], h1);
    }
    h0 = fmaxf(h0, 0.f);
    h1 = fmaxf(h1, 0.f);

    float l0 = h0 * sW2[lane * 3 + 0] + h1 * sW2[(lane + 32) * 3 + 0];
    float l1 = h0 * sW2[lane * 3 + 1] + h1 * sW2[(lane + 32) * 3 + 1];
    float l2 = h0 * sW2[lane * 3 + 2] + h1 * sW2[(lane + 32) * 3 + 2];
#pragma unroll
    for (int o = 16; o > 0; o >>= 1) {
        l0 += __shfl_xor_sync(0xffffffffu, l0, o);
        l1 += __shfl_xor_sync(0xffffffffu, l1, o);
        l2 += __shfl_xor_sync(0xffffffffu, l2, o);
    }
    if (lane == 0) {
        l0 += sb2[0]; l1 += sb2[1]; l2 += sb2[2];
        float m = fmaxf(l0, fmaxf(l1, l2));
        float lse = m + logf(expf(l0 - m) + expf(l1 - m) + expf(l2 - m));
        out[gi * 3 + 0] = l0 - lse;
        out[gi * 3 + 1] = l1 - lse;
        out[gi * 3 + 2] = l2 - lse;
    }
}

extern "C" void kernel_launch(void* const* d_in, const int* in_sizes, int n_in,
                              void* d_out, int out_size)
{
    const float* x     = (const float*)d_in[0];
    const int*   ei    = (const int*)  d_in[1];
    const int*   batch = (const int*)  d_in[2];
    const float* Wr1 = (const float*)d_in[3];
    const float* br1 = (const float*)d_in[4];
    const float* Ws1 = (const float*)d_in[5];
    const float* Wr2 = (const float*)d_in[6];
    const float* br2 = (const float*)d_in[7];
    const float* Ws2 = (const float*)d_in[8];
    const float* Wr3 = (const float*)d_in[9];
    const float* br3 = (const float*)d_in[10];
    const float* Ws3 = (const float*)d_in[11];
    const float* Wf1 = (const float*)d_in[12];
    const float* bf1 = (const float*)d_in[13];
    const float* Wf2 = (const float*)d_in[14];
    const float* bf2 = (const float*)d_in[15];

    int n = in_sizes[0] / DD;     // 100000
    int E = in_sizes[1] / 2;      // 1200000
    const int* src = ei;
    const int* dst = ei + E;

    float *t, *bufA, *bufB;
    cudaGetSymbolAddress((void**)&t,    d_t);
    cudaGetSymbolAddress((void**)&bufA, d_bufA);
    cudaGetSymbolAddress((void**)&bufB, d_bufB);

    int gemm_grid   = (n + BM - 1) / BM;
    int gather_grid = (n + 7) / 8;
    int edge_grid   = (E + 255) / 256;
    int scan_blocks = (n + 1023) / 1024;       // 98

    // --- CSR build (per launch; graph-capturable) ---
    zero_kernel<<<(NN + 255) / 256, 256>>>();
    hist_kernel<<<edge_grid, 256>>>(dst, E);
    scan1_kernel<<<scan_blocks, 1024>>>(n);
    scan2_kernel<<<1, 128>>>(scan_blocks);
    scan3_kernel<<<scan_blocks, 1024>>>(n, E);
    fill_kernel<<<edge_grid, 256>>>(src, dst, E);

    // --- 3 GraphConv layers (relu folded into gather write) ---
    gemm2_kernel<<<gemm_grid, 256>>>(x, Wr1, br1, Ws1, t, bufA, n);
    gather_kernel<<<gather_grid, 256>>>(t, bufA, bufA, batch, n, 0);
    gemm2_kernel<<<gemm_grid, 256>>>(bufA, Wr2, br2, Ws2, t, bufB, n);
    gather_kernel<<<gather_grid, 256>>>(t, bufB, bufB, batch, n, 0);
    gemm2_kernel<<<gemm_grid, 256>>>(bufB, Wr3, br3, Ws3, t, bufA, n);
    // layer-3 gather fused with global-add-pool (writes d_g, no h3 buffer)
    gather_kernel<<<gather_grid, 256>>>(t, bufA, nullptr, batch, n, 1);

    head_kernel<<<32, 128>>>(Wf1, bf1, Wf2, bf2, (float*)d_out);
}